// round 10
// baseline (speedup 1.0000x reference)
#include <cuda_runtime.h>
#include <cstdint>
#include <cstddef>

// Problem dims
#define D_DIM 2048
#define F_DIM 512
#define B_DIM 32
#define R_DIM 10          // Taylor terms r = 0..9 (|z| <= ~2.05)
#define R_PAD 12          // storage stride (keeps float4 alignment)
#define NDQ 16            // d-slices for stage A partials (128 d per slice)

// Scratch
__device__ float g_abssum[D_DIM];
__device__ float g_gj[D_DIM];                          // exp(-abs_sum_j)
__device__ float g_m[R_DIM];                           // moments sum_j g_j v_j^r
__device__ __align__(16) float g_ca[D_DIM * R_PAD];    // u_d^r / Z_d
__device__ __align__(16) float g_cb[D_DIM * R_PAD];    // g_j * v_j^r / r!
__device__ __align__(16) float g_ypart[(size_t)NDQ * B_DIM * R_DIM * F_DIM];
__device__ __align__(16) float g_y[(size_t)B_DIM * R_DIM * F_DIM];

__constant__ float c_invfact[R_DIM] = {
    1.0f, 1.0f, 0.5f, 1.0f/6.0f, 1.0f/24.0f, 1.0f/120.0f,
    1.0f/720.0f, 1.0f/5040.0f, 1.0f/40320.0f, 1.0f/362880.0f};

__device__ __forceinline__ float warpSum(float v) {
    #pragma unroll
    for (int o = 16; o; o >>= 1) v += __shfl_xor_sync(0xffffffffu, v, o);
    return v;
}

// ---------------------------------------------------------------------------
// K1: abs_sum[j] = sum_k |s[j] - s[k]|, and g_j = exp(-abs_sum[j])
// ---------------------------------------------------------------------------
__global__ void abssum_kernel(const float* __restrict__ s) {
    __shared__ float ss[D_DIM];
    int tid = threadIdx.x;
    for (int k = tid; k < D_DIM; k += 256) ss[k] = s[k];
    __syncthreads();
    int j = blockIdx.x * 256 + tid;
    float sj = ss[j];
    float a0 = 0.f, a1 = 0.f, a2 = 0.f, a3 = 0.f;
    #pragma unroll 4
    for (int k = 0; k < D_DIM; k += 4) {
        a0 += fabsf(sj - ss[k + 0]);
        a1 += fabsf(sj - ss[k + 1]);
        a2 += fabsf(sj - ss[k + 2]);
        a3 += fabsf(sj - ss[k + 3]);
    }
    float a = (a0 + a1) + (a2 + a3);
    g_abssum[j] = a;
    g_gj[j] = expf(-a);
}

// ---------------------------------------------------------------------------
// K2: single CTA. moments m[r] = sum_j g_j * v_j^r  (v_j = 1024*s_j, r=0..9)
// ---------------------------------------------------------------------------
__global__ void __launch_bounds__(1024)
moments_kernel(const float* __restrict__ s) {
    __shared__ float red[32][R_DIM];
    int tid = threadIdx.x, warp = tid >> 5, lane = tid & 31;

    float m[R_DIM];
    #pragma unroll
    for (int r = 0; r < R_DIM; r++) m[r] = 0.f;

    #pragma unroll
    for (int h = 0; h < 2; h++) {
        int j = tid + h * 1024;
        float g = g_gj[j];
        float v = 1024.0f * s[j];
        float p = g;
        #pragma unroll
        for (int r = 0; r < R_DIM; r++) { m[r] += p; p *= v; }
    }
    #pragma unroll
    for (int r = 0; r < R_DIM; r++) {
        float v = warpSum(m[r]);
        if (lane == 0) red[warp][r] = v;
    }
    __syncthreads();
    if (tid < R_DIM) {
        float a = 0.f;
        #pragma unroll
        for (int w = 0; w < 32; w++) a += red[w][tid];
        g_m[tid] = a;
    }
}

// ---------------------------------------------------------------------------
// K3: per-index coefficients (one thread per i):
//   Z_i = sum_r (u_i^r / r!) * m_r          (u_i = (2047-2i)/1024)
//   ca[i][r] = u_i^r / Z_i
//   cb[i][r] = g_i * v_i^r / r!             (v_i = 1024*s_i)
// ---------------------------------------------------------------------------
__global__ void coeff_kernel(const float* __restrict__ s) {
    int i = blockIdx.x * 256 + threadIdx.x;
    float u = (2047.0f - 2.0f * (float)i) * (1.0f / 1024.0f);
    float up[R_DIM];
    up[0] = 1.0f;
    #pragma unroll
    for (int r = 1; r < R_DIM; r++) up[r] = up[r - 1] * u;
    float Z = 0.f;
    #pragma unroll
    for (int r = 0; r < R_DIM; r++) Z = fmaf(up[r] * c_invfact[r], g_m[r], Z);
    float winv = 1.0f / Z;

    float v = 1024.0f * s[i];
    float pv = g_gj[i];
    #pragma unroll
    for (int r = 0; r < R_DIM; r++) {
        g_ca[i * R_PAD + r] = winv * up[r];
        g_cb[i * R_PAD + r] = pv * c_invfact[r];
        pv *= v;
    }
}

// ---------------------------------------------------------------------------
// K4 stage A: y_part[dq][b][r][f] = sum_{d in slice of 128} ca[d][r]*x[b][d][f]
// grid (NDQ, B) = (16, 32) = 512 CTAs. 256 thr = 128 f4-cols x 2 halves of 64 d.
// ---------------------------------------------------------------------------
__global__ void __launch_bounds__(256)
stageA_kernel(const float* __restrict__ x) {
    __shared__ __align__(16) float sca[128 * R_PAD];          // 6 KB
    __shared__ __align__(16) float4 sred[128 * R_DIM];        // 20 KB
    const int dq = blockIdx.x, b = blockIdx.y;
    const int tid = threadIdx.x;
    const int d0 = dq * 128;

    for (int k = tid; k < 128 * R_PAD; k += 256)
        sca[k] = g_ca[d0 * R_PAD + k];
    __syncthreads();

    const int f4 = tid & 127;
    const int half = tid >> 7;

    float4 acc[R_DIM];
    #pragma unroll
    for (int r = 0; r < R_DIM; r++) acc[r] = make_float4(0.f, 0.f, 0.f, 0.f);

    const float4* xp = reinterpret_cast<const float4*>(
        x + ((size_t)b * D_DIM + d0 + half * 64) * F_DIM) + f4;

    #pragma unroll 4
    for (int dd = 0; dd < 64; dd++) {
        float4 xv = xp[(size_t)dd * (F_DIM / 4)];
        const float* cb_ = &sca[(half * 64 + dd) * R_PAD];
        float4 c0 = *reinterpret_cast<const float4*>(cb_);
        float4 c1 = *reinterpret_cast<const float4*>(cb_ + 4);
        float2 c2 = *reinterpret_cast<const float2*>(cb_ + 8);
        const float cr[R_DIM] = {c0.x, c0.y, c0.z, c0.w,
                                 c1.x, c1.y, c1.z, c1.w,
                                 c2.x, c2.y};
        #pragma unroll
        for (int r = 0; r < R_DIM; r++) {
            acc[r].x = fmaf(cr[r], xv.x, acc[r].x);
            acc[r].y = fmaf(cr[r], xv.y, acc[r].y);
            acc[r].z = fmaf(cr[r], xv.z, acc[r].z);
            acc[r].w = fmaf(cr[r], xv.w, acc[r].w);
        }
    }

    if (half == 1) {
        #pragma unroll
        for (int r = 0; r < R_DIM; r++) sred[f4 * R_DIM + r] = acc[r];
    }
    __syncthreads();
    if (half == 0) {
        float4* yp = reinterpret_cast<float4*>(
            g_ypart + (((size_t)dq * B_DIM + b) * R_DIM) * F_DIM) + f4;
        #pragma unroll
        for (int r = 0; r < R_DIM; r++) {
            float4 o = sred[f4 * R_DIM + r];
            o.x += acc[r].x; o.y += acc[r].y; o.z += acc[r].z; o.w += acc[r].w;
            yp[(size_t)r * (F_DIM / 4)] = o;
        }
    }
}

// ---------------------------------------------------------------------------
// K5: y[b][r][f] = sum_dq y_part[dq][b][r][f]
// grid (B, R): one (b, r) row per CTA of 128 threads.
// ---------------------------------------------------------------------------
__global__ void __launch_bounds__(128)
combine_kernel() {
    const int b = blockIdx.x, r = blockIdx.y;
    const int k = threadIdx.x;           // f4 index 0..127
    const size_t row = ((size_t)b * R_DIM + r) * F_DIM;
    float4 a = make_float4(0.f, 0.f, 0.f, 0.f);
    #pragma unroll
    for (int dq = 0; dq < NDQ; dq++) {
        const float4* yp = reinterpret_cast<const float4*>(
            g_ypart + ((size_t)dq * B_DIM * R_DIM) * F_DIM + row);
        float4 p = yp[k];
        a.x += p.x; a.y += p.y; a.z += p.z; a.w += p.w;
    }
    reinterpret_cast<float4*>(g_y + row)[k] = a;
}

// ---------------------------------------------------------------------------
// K6 stage B: out[b][j][f] = sum_r cb[j][r] * y[b][r][f]
// grid (16 j-tiles, B, 2 f-halves) = 1024 CTAs. 8 warps; warp w owns
// j in [w*16, w*16+16); lanes sweep 64 f4-cols of this half in 2 chunks of 32.
// ---------------------------------------------------------------------------
__global__ void __launch_bounds__(256)
stageB_kernel(float* __restrict__ out) {
    __shared__ __align__(16) float sy[R_DIM * (F_DIM / 2)];   // 10 KB
    __shared__ __align__(16) float scb[128 * R_PAD];          // 6 KB
    const int jt = blockIdx.x, b = blockIdx.y, fh = blockIdx.z;
    const int tid = threadIdx.x;
    const int wid = tid >> 5, lane = tid & 31;
    const int F2 = F_DIM / 2;

    for (int k = tid; k < R_DIM * F2; k += 256) {
        int r = k / F2, f = k - r * F2;
        sy[k] = g_y[(size_t)b * R_DIM * F_DIM + (size_t)r * F_DIM + fh * F2 + f];
    }
    for (int k = tid; k < 128 * R_PAD; k += 256)
        scb[k] = g_cb[(size_t)(jt * 128) * R_PAD + k];
    __syncthreads();

    float* ob = out + ((size_t)b * D_DIM + jt * 128) * F_DIM + fh * F2;

    #pragma unroll 1
    for (int fc = 0; fc < 2; fc++) {
        const int f4 = fc * 32 + lane;      // 0..63 within this half
        float4 yr[R_DIM];
        #pragma unroll
        for (int r = 0; r < R_DIM; r++)
            yr[r] = reinterpret_cast<const float4*>(&sy[r * F2])[f4];
        #pragma unroll 2
        for (int ji = 0; ji < 16; ji++) {
            const int jl = wid * 16 + ji;
            const float* cb_ = &scb[jl * R_PAD];
            float4 c0 = *reinterpret_cast<const float4*>(cb_);
            float4 c1 = *reinterpret_cast<const float4*>(cb_ + 4);
            float2 c2 = *reinterpret_cast<const float2*>(cb_ + 8);
            const float cr[R_DIM] = {c0.x, c0.y, c0.z, c0.w,
                                     c1.x, c1.y, c1.z, c1.w,
                                     c2.x, c2.y};
            float4 o = make_float4(0.f, 0.f, 0.f, 0.f);
            #pragma unroll
            for (int r = 0; r < R_DIM; r++) {
                o.x = fmaf(cr[r], yr[r].x, o.x);
                o.y = fmaf(cr[r], yr[r].y, o.y);
                o.z = fmaf(cr[r], yr[r].z, o.z);
                o.w = fmaf(cr[r], yr[r].w, o.w);
            }
            reinterpret_cast<float4*>(ob + (size_t)jl * F_DIM)[f4] = o;
        }
    }
}

// ---------------------------------------------------------------------------
// launch
// ---------------------------------------------------------------------------
extern "C" void kernel_launch(void* const* d_in, const int* in_sizes, int n_in,
                              void* d_out, int out_size) {
    const float* x;
    const float* s;
    if (in_sizes[0] == D_DIM) {
        s = (const float*)d_in[0];
        x = (const float*)d_in[1];
    } else {
        x = (const float*)d_in[0];
        s = (const float*)d_in[1];
    }
    float* out = (float*)d_out;

    abssum_kernel<<<D_DIM / 256, 256>>>(s);
    moments_kernel<<<1, 1024>>>(s);
    coeff_kernel<<<D_DIM / 256, 256>>>(s);
    stageA_kernel<<<dim3(NDQ, B_DIM), 256>>>(x);
    combine_kernel<<<dim3(B_DIM, R_DIM), 128>>>();
    stageB_kernel<<<dim3(D_DIM / 128, B_DIM, 2), 256>>>(out);
}

// round 13
// speedup vs baseline: 1.1119x; 1.1119x over previous
#include <cuda_runtime.h>
#include <cstdint>
#include <cstddef>

// Problem dims
#define D_DIM 2048
#define F_DIM 512
#define B_DIM 32
#define R_DIM 10          // Taylor terms r = 0..9 (|z| <= ~2.05)
#define R_PAD 12          // storage stride for coeff arrays
#define NDQ 16            // d-slices for stage A partials (128 d per slice)

typedef unsigned long long ull;

// Scratch
__device__ float g_abssum[D_DIM];
__device__ float g_gj[D_DIM];                          // exp(-abs_sum_j)
__device__ float g_m[R_DIM];                           // moments sum_j g_j v_j^r
__device__ __align__(16) float g_ca[D_DIM * R_PAD];    // u_d^r / Z_d
__device__ __align__(16) float g_cb[D_DIM * R_PAD];    // g_j * v_j^r / r!
__device__ __align__(16) float g_ypart[(size_t)NDQ * B_DIM * R_DIM * F_DIM];
__device__ __align__(16) float g_y[(size_t)B_DIM * R_DIM * F_DIM];

__constant__ float c_invfact[R_DIM] = {
    1.0f, 1.0f, 0.5f, 1.0f/6.0f, 1.0f/24.0f, 1.0f/120.0f,
    1.0f/720.0f, 1.0f/5040.0f, 1.0f/40320.0f, 1.0f/362880.0f};

// ---------------------------------------------------------------------------
// packed f32x2 helpers (PTX ISA 8.6 sm_100-family baseline; NOT an "a"-gated
// feature — a ptxas rejection would surface as rc!=0 with error text, which
// we have not observed)
// ---------------------------------------------------------------------------
__device__ __forceinline__ ull fma2(ull a, ull b, ull c) {
    ull d;
    asm("fma.rn.f32x2 %0, %1, %2, %3;" : "=l"(d) : "l"(a), "l"(b), "l"(c));
    return d;
}
__device__ __forceinline__ ull add2(ull a, ull b) {
    ull d;
    asm("add.rn.f32x2 %0, %1, %2;" : "=l"(d) : "l"(a), "l"(b));
    return d;
}

__device__ __forceinline__ float warpSum(float v) {
    #pragma unroll
    for (int o = 16; o; o >>= 1) v += __shfl_xor_sync(0xffffffffu, v, o);
    return v;
}

// ---------------------------------------------------------------------------
// K1: abs_sum[j] = sum_k |s[j] - s[k]|, and g_j = exp(-abs_sum[j])
// ---------------------------------------------------------------------------
__global__ void abssum_kernel(const float* __restrict__ s) {
    __shared__ float ss[D_DIM];
    int tid = threadIdx.x;
    for (int k = tid; k < D_DIM; k += 256) ss[k] = s[k];
    __syncthreads();
    int j = blockIdx.x * 256 + tid;
    float sj = ss[j];
    float a0 = 0.f, a1 = 0.f, a2 = 0.f, a3 = 0.f;
    #pragma unroll 4
    for (int k = 0; k < D_DIM; k += 4) {
        a0 += fabsf(sj - ss[k + 0]);
        a1 += fabsf(sj - ss[k + 1]);
        a2 += fabsf(sj - ss[k + 2]);
        a3 += fabsf(sj - ss[k + 3]);
    }
    float a = (a0 + a1) + (a2 + a3);
    g_abssum[j] = a;
    g_gj[j] = expf(-a);
}

// ---------------------------------------------------------------------------
// K2: single CTA. moments m[r] = sum_j g_j * v_j^r  (v_j = 1024*s_j)
// ---------------------------------------------------------------------------
__global__ void __launch_bounds__(1024)
moments_kernel(const float* __restrict__ s) {
    __shared__ float red[32][R_DIM];
    int tid = threadIdx.x, warp = tid >> 5, lane = tid & 31;

    float m[R_DIM];
    #pragma unroll
    for (int r = 0; r < R_DIM; r++) m[r] = 0.f;

    #pragma unroll
    for (int h = 0; h < 2; h++) {
        int j = tid + h * 1024;
        float g = g_gj[j];
        float v = 1024.0f * s[j];
        float p = g;
        #pragma unroll
        for (int r = 0; r < R_DIM; r++) { m[r] += p; p *= v; }
    }
    #pragma unroll
    for (int r = 0; r < R_DIM; r++) {
        float v = warpSum(m[r]);
        if (lane == 0) red[warp][r] = v;
    }
    __syncthreads();
    if (tid < R_DIM) {
        float a = 0.f;
        #pragma unroll
        for (int w = 0; w < 32; w++) a += red[w][tid];
        g_m[tid] = a;
    }
}

// ---------------------------------------------------------------------------
// K3: per-index coefficients (one thread per i)
//   Z_i = sum_r (u_i^r / r!) * m_r          (u_i = (2047-2i)/1024)
//   ca[i][r] = u_i^r / Z_i
//   cb[i][r] = g_i * v_i^r / r!             (v_i = 1024*s_i)
// ---------------------------------------------------------------------------
__global__ void coeff_kernel(const float* __restrict__ s) {
    int i = blockIdx.x * 256 + threadIdx.x;
    float u = (2047.0f - 2.0f * (float)i) * (1.0f / 1024.0f);
    float up[R_DIM];
    up[0] = 1.0f;
    #pragma unroll
    for (int r = 1; r < R_DIM; r++) up[r] = up[r - 1] * u;
    float Z = 0.f;
    #pragma unroll
    for (int r = 0; r < R_DIM; r++) Z = fmaf(up[r] * c_invfact[r], g_m[r], Z);
    float winv = 1.0f / Z;

    float v = 1024.0f * s[i];
    float pv = g_gj[i];
    #pragma unroll
    for (int r = 0; r < R_DIM; r++) {
        g_ca[i * R_PAD + r] = winv * up[r];
        g_cb[i * R_PAD + r] = pv * c_invfact[r];
        pv *= v;
    }
}

// ---------------------------------------------------------------------------
// K4 stage A: y_part[dq][b][r][f] = sum_{d in slice of 128} ca[d][r]*x[b][d][f]
// grid (NDQ, B) = (16, 32). 256 thr = 128 f4-cols x 2 halves of 64 d.
// Packed f32x2 FMA; coeffs pre-duplicated {c,c}; 4-deep LDG prefetch ring.
// ---------------------------------------------------------------------------
__global__ void __launch_bounds__(256)
stageA_kernel(const float* __restrict__ x) {
    __shared__ __align__(16) float2 sca2[128 * R_DIM];        // 10 KB, {c,c}
    __shared__ __align__(16) ulonglong2 sred[128 * R_DIM];    // 20 KB
    const int dq = blockIdx.x, b = blockIdx.y;
    const int tid = threadIdx.x;
    const int d0 = dq * 128;

    for (int k = tid; k < 128 * R_DIM; k += 256) {
        int d = k / R_DIM, r = k - d * R_DIM;
        float c = g_ca[(size_t)(d0 + d) * R_PAD + r];
        sca2[k] = make_float2(c, c);
    }
    __syncthreads();

    const int f4 = tid & 127;
    const int half = tid >> 7;

    ull accXY[R_DIM], accZW[R_DIM];
    #pragma unroll
    for (int r = 0; r < R_DIM; r++) { accXY[r] = 0ull; accZW[r] = 0ull; }

    const ulonglong2* xp = reinterpret_cast<const ulonglong2*>(
        x + ((size_t)b * D_DIM + d0 + half * 64) * F_DIM) + f4;

    ulonglong2 buf[4];
    #pragma unroll
    for (int q = 0; q < 4; q++) buf[q] = xp[(size_t)q * (F_DIM / 4)];

    #pragma unroll 2
    for (int dd = 0; dd < 64; dd += 4) {
        #pragma unroll
        for (int q = 0; q < 4; q++) {
            ulonglong2 xv = buf[q];
            int nx = dd + 4 + q;
            if (nx < 64) buf[q] = xp[(size_t)nx * (F_DIM / 4)];
            const ulonglong2* cp = reinterpret_cast<const ulonglong2*>(
                sca2 + (half * 64 + dd + q) * R_DIM);
            ulonglong2 u0 = cp[0], u1 = cp[1], u2 = cp[2], u3 = cp[3], u4 = cp[4];
            const ull c[R_DIM] = {u0.x, u0.y, u1.x, u1.y, u2.x,
                                  u2.y, u3.x, u3.y, u4.x, u4.y};
            #pragma unroll
            for (int r = 0; r < R_DIM; r++) {
                accXY[r] = fma2(xv.x, c[r], accXY[r]);
                accZW[r] = fma2(xv.y, c[r], accZW[r]);
            }
        }
    }

    if (half == 1) {
        #pragma unroll
        for (int r = 0; r < R_DIM; r++) {
            ulonglong2 v; v.x = accXY[r]; v.y = accZW[r];
            sred[f4 * R_DIM + r] = v;
        }
    }
    __syncthreads();
    if (half == 0) {
        ulonglong2* yp = reinterpret_cast<ulonglong2*>(
            g_ypart + (((size_t)dq * B_DIM + b) * R_DIM) * F_DIM) + f4;
        #pragma unroll
        for (int r = 0; r < R_DIM; r++) {
            ulonglong2 o = sred[f4 * R_DIM + r];
            o.x = add2(o.x, accXY[r]);
            o.y = add2(o.y, accZW[r]);
            yp[(size_t)r * (F_DIM / 4)] = o;
        }
    }
}

// ---------------------------------------------------------------------------
// K5: y[b][r][f] = sum_dq y_part[dq][b][r][f]
// grid (B, R): one (b, r) row per CTA of 128 threads.
// ---------------------------------------------------------------------------
__global__ void __launch_bounds__(128)
combine_kernel() {
    const int b = blockIdx.x, r = blockIdx.y;
    const int k = threadIdx.x;           // f4 index 0..127
    const size_t row = ((size_t)b * R_DIM + r) * F_DIM;
    ulonglong2 a; a.x = 0ull; a.y = 0ull;
    #pragma unroll
    for (int dq = 0; dq < NDQ; dq++) {
        const ulonglong2* yp = reinterpret_cast<const ulonglong2*>(
            g_ypart + ((size_t)dq * B_DIM * R_DIM) * F_DIM + row);
        ulonglong2 p = yp[k];
        a.x = add2(a.x, p.x);
        a.y = add2(a.y, p.y);
    }
    reinterpret_cast<ulonglong2*>(g_y + row)[k] = a;
}

// ---------------------------------------------------------------------------
// K6 stage B: out[b][j][f] = sum_r cb[j][r] * y[b][r][f]
// grid (16 j-tiles, B, 2 f-halves). Packed f32x2 FMA, duplicated coeffs.
// ---------------------------------------------------------------------------
__global__ void __launch_bounds__(256)
stageB_kernel(float* __restrict__ out) {
    __shared__ __align__(16) float sy[R_DIM * (F_DIM / 2)];   // 10 KB
    __shared__ __align__(16) float2 scb2[128 * R_DIM];        // 10 KB, {c,c}
    const int jt = blockIdx.x, b = blockIdx.y, fh = blockIdx.z;
    const int tid = threadIdx.x;
    const int wid = tid >> 5, lane = tid & 31;
    const int F2 = F_DIM / 2;

    for (int k = tid; k < R_DIM * F2; k += 256) {
        int r = k / F2, f = k - r * F2;
        sy[k] = g_y[(size_t)b * R_DIM * F_DIM + (size_t)r * F_DIM + fh * F2 + f];
    }
    for (int k = tid; k < 128 * R_DIM; k += 256) {
        int j = k / R_DIM, r = k - j * R_DIM;
        float c = g_cb[(size_t)(jt * 128 + j) * R_PAD + r];
        scb2[k] = make_float2(c, c);
    }
    __syncthreads();

    float* ob = out + ((size_t)b * D_DIM + jt * 128) * F_DIM + fh * F2;

    #pragma unroll 1
    for (int fc = 0; fc < 2; fc++) {
        const int f4 = fc * 32 + lane;      // 0..63 within this half
        ull yXY[R_DIM], yZW[R_DIM];
        #pragma unroll
        for (int r = 0; r < R_DIM; r++) {
            ulonglong2 v = reinterpret_cast<const ulonglong2*>(&sy[r * F2])[f4];
            yXY[r] = v.x; yZW[r] = v.y;
        }
        #pragma unroll 2
        for (int ji = 0; ji < 16; ji++) {
            const int jl = wid * 16 + ji;
            const ulonglong2* cp = reinterpret_cast<const ulonglong2*>(
                scb2 + jl * R_DIM);
            ulonglong2 u0 = cp[0], u1 = cp[1], u2 = cp[2], u3 = cp[3], u4 = cp[4];
            const ull c[R_DIM] = {u0.x, u0.y, u1.x, u1.y, u2.x,
                                  u2.y, u3.x, u3.y, u4.x, u4.y};
            ull oXY = 0ull, oZW = 0ull;
            #pragma unroll
            for (int r = 0; r < R_DIM; r++) {
                oXY = fma2(yXY[r], c[r], oXY);
                oZW = fma2(yZW[r], c[r], oZW);
            }
            ulonglong2 o; o.x = oXY; o.y = oZW;
            reinterpret_cast<ulonglong2*>(ob + (size_t)jl * F_DIM)[f4] = o;
        }
    }
}

// ---------------------------------------------------------------------------
// launch
// ---------------------------------------------------------------------------
extern "C" void kernel_launch(void* const* d_in, const int* in_sizes, int n_in,
                              void* d_out, int out_size) {
    const float* x;
    const float* s;
    if (in_sizes[0] == D_DIM) {
        s = (const float*)d_in[0];
        x = (const float*)d_in[1];
    } else {
        x = (const float*)d_in[0];
        s = (const float*)d_in[1];
    }
    float* out = (float*)d_out;

    abssum_kernel<<<D_DIM / 256, 256>>>(s);
    moments_kernel<<<1, 1024>>>(s);
    coeff_kernel<<<D_DIM / 256, 256>>>(s);
    stageA_kernel<<<dim3(NDQ, B_DIM), 256>>>(x);
    combine_kernel<<<dim3(B_DIM, R_DIM), 128>>>();
    stageB_kernel<<<dim3(D_DIM / 128, B_DIM, 2), 256>>>(out);
}

// round 14
// speedup vs baseline: 1.1614x; 1.0445x over previous
#include <cuda_runtime.h>
#include <cstdint>
#include <cstddef>

// Problem dims
#define D_DIM 2048
#define F_DIM 512
#define B_DIM 32
#define R_DIM 10          // Taylor terms r = 0..9 (|z| <= ~2.05)
#define R_HALF 5          // r-split: 5 terms per thread-half
#define R_PAD 12          // storage stride for coeff arrays
#define NDQ 16            // d-slices for stage A partials (128 d per slice)

typedef unsigned long long ull;

// Scratch
__device__ float g_abssum[D_DIM];
__device__ float g_gj[D_DIM];                          // exp(-abs_sum_j)
__device__ float g_m[R_DIM];                           // moments sum_j g_j v_j^r
__device__ __align__(16) float g_ca[D_DIM * R_PAD];    // u_d^r / Z_d
__device__ __align__(16) float g_cb[D_DIM * R_PAD];    // g_j * v_j^r / r!
__device__ __align__(16) float g_ypart[(size_t)NDQ * B_DIM * R_DIM * F_DIM];
__device__ __align__(16) float g_y[(size_t)B_DIM * R_DIM * F_DIM];

__constant__ float c_invfact[R_DIM] = {
    1.0f, 1.0f, 0.5f, 1.0f/6.0f, 1.0f/24.0f, 1.0f/120.0f,
    1.0f/720.0f, 1.0f/5040.0f, 1.0f/40320.0f, 1.0f/362880.0f};

// ---------------------------------------------------------------------------
// packed f32x2 helpers
// ---------------------------------------------------------------------------
__device__ __forceinline__ ull fma2(ull a, ull b, ull c) {
    ull d;
    asm("fma.rn.f32x2 %0, %1, %2, %3;" : "=l"(d) : "l"(a), "l"(b), "l"(c));
    return d;
}
__device__ __forceinline__ ull add2(ull a, ull b) {
    ull d;
    asm("add.rn.f32x2 %0, %1, %2;" : "=l"(d) : "l"(a), "l"(b));
    return d;
}

__device__ __forceinline__ float warpSum(float v) {
    #pragma unroll
    for (int o = 16; o; o >>= 1) v += __shfl_xor_sync(0xffffffffu, v, o);
    return v;
}

// ---------------------------------------------------------------------------
// K1: abs_sum[j] = sum_k |s[j] - s[k]|, and g_j = exp(-abs_sum[j])
// ---------------------------------------------------------------------------
__global__ void abssum_kernel(const float* __restrict__ s) {
    __shared__ float ss[D_DIM];
    int tid = threadIdx.x;
    for (int k = tid; k < D_DIM; k += 256) ss[k] = s[k];
    __syncthreads();
    int j = blockIdx.x * 256 + tid;
    float sj = ss[j];
    float a0 = 0.f, a1 = 0.f, a2 = 0.f, a3 = 0.f;
    #pragma unroll 4
    for (int k = 0; k < D_DIM; k += 4) {
        a0 += fabsf(sj - ss[k + 0]);
        a1 += fabsf(sj - ss[k + 1]);
        a2 += fabsf(sj - ss[k + 2]);
        a3 += fabsf(sj - ss[k + 3]);
    }
    float a = (a0 + a1) + (a2 + a3);
    g_abssum[j] = a;
    g_gj[j] = expf(-a);
}

// ---------------------------------------------------------------------------
// K2: single CTA. moments m[r] = sum_j g_j * v_j^r  (v_j = 1024*s_j)
// ---------------------------------------------------------------------------
__global__ void __launch_bounds__(1024)
moments_kernel(const float* __restrict__ s) {
    __shared__ float red[32][R_DIM];
    int tid = threadIdx.x, warp = tid >> 5, lane = tid & 31;

    float m[R_DIM];
    #pragma unroll
    for (int r = 0; r < R_DIM; r++) m[r] = 0.f;

    #pragma unroll
    for (int h = 0; h < 2; h++) {
        int j = tid + h * 1024;
        float g = g_gj[j];
        float v = 1024.0f * s[j];
        float p = g;
        #pragma unroll
        for (int r = 0; r < R_DIM; r++) { m[r] += p; p *= v; }
    }
    #pragma unroll
    for (int r = 0; r < R_DIM; r++) {
        float v = warpSum(m[r]);
        if (lane == 0) red[warp][r] = v;
    }
    __syncthreads();
    if (tid < R_DIM) {
        float a = 0.f;
        #pragma unroll
        for (int w = 0; w < 32; w++) a += red[w][tid];
        g_m[tid] = a;
    }
}

// ---------------------------------------------------------------------------
// K3: per-index coefficients (one thread per i)
// ---------------------------------------------------------------------------
__global__ void coeff_kernel(const float* __restrict__ s) {
    int i = blockIdx.x * 256 + threadIdx.x;
    float u = (2047.0f - 2.0f * (float)i) * (1.0f / 1024.0f);
    float up[R_DIM];
    up[0] = 1.0f;
    #pragma unroll
    for (int r = 1; r < R_DIM; r++) up[r] = up[r - 1] * u;
    float Z = 0.f;
    #pragma unroll
    for (int r = 0; r < R_DIM; r++) Z = fmaf(up[r] * c_invfact[r], g_m[r], Z);
    float winv = 1.0f / Z;

    float v = 1024.0f * s[i];
    float pv = g_gj[i];
    #pragma unroll
    for (int r = 0; r < R_DIM; r++) {
        g_ca[i * R_PAD + r] = winv * up[r];
        g_cb[i * R_PAD + r] = pv * c_invfact[r];
        pv *= v;
    }
}

// ---------------------------------------------------------------------------
// K4 stage A: y_part[dq][b][r][f] = sum_{d in slice of 128} ca[d][r]*x[b][d][f]
// grid (NDQ, B) = (16, 32). 256 thr = 128 f4-cols x 2 r-halves (r=0..4 / 5..9).
// Each half sweeps ALL 128 d rows (second reader hits L1/L2; DRAM unchanged).
// No cross-thread reduction needed: r-outputs disjoint. f32x2 FMA, 4-deep ring.
// Coeffs per-half layout [rh][128][6] float2 (48B row stride, 16B-aligned).
// ---------------------------------------------------------------------------
__global__ void __launch_bounds__(256)
stageA_kernel(const float* __restrict__ x) {
    __shared__ __align__(16) float2 sca2[2 * 128 * 6];        // 12 KB, {c,c}
    const int dq = blockIdx.x, b = blockIdx.y;
    const int tid = threadIdx.x;
    const int d0 = dq * 128;

    for (int k = tid; k < 128 * R_DIM; k += 256) {
        int d = k / R_DIM, r = k - d * R_DIM;
        float c = g_ca[(size_t)(d0 + d) * R_PAD + r];
        int rh = r / R_HALF, rr = r - rh * R_HALF;
        sca2[(rh * 128 + d) * 6 + rr] = make_float2(c, c);
    }
    __syncthreads();

    const int f4 = tid & 127;
    const int rh = tid >> 7;          // 0: r=0..4, 1: r=5..9

    ull accXY[R_HALF], accZW[R_HALF];
    #pragma unroll
    for (int r = 0; r < R_HALF; r++) { accXY[r] = 0ull; accZW[r] = 0ull; }

    const ulonglong2* xp = reinterpret_cast<const ulonglong2*>(
        x + ((size_t)b * D_DIM + d0) * F_DIM) + f4;
    const ull* cbase = reinterpret_cast<const ull*>(sca2 + rh * 128 * 6);

    ulonglong2 buf[4];
    #pragma unroll
    for (int q = 0; q < 4; q++) buf[q] = xp[(size_t)q * (F_DIM / 4)];

    #pragma unroll 2
    for (int dd = 0; dd < 128; dd += 4) {
        #pragma unroll
        for (int q = 0; q < 4; q++) {
            ulonglong2 xv = buf[q];
            int nx = dd + 4 + q;
            if (nx < 128) buf[q] = xp[(size_t)nx * (F_DIM / 4)];
            const ull* cp = cbase + (dd + q) * 6;
            ulonglong2 p01 = *reinterpret_cast<const ulonglong2*>(cp);
            ulonglong2 p23 = *reinterpret_cast<const ulonglong2*>(cp + 2);
            ull p4 = cp[4];
            const ull c[R_HALF] = {p01.x, p01.y, p23.x, p23.y, p4};
            #pragma unroll
            for (int r = 0; r < R_HALF; r++) {
                accXY[r] = fma2(xv.x, c[r], accXY[r]);
                accZW[r] = fma2(xv.y, c[r], accZW[r]);
            }
        }
    }

    ulonglong2* yp = reinterpret_cast<ulonglong2*>(
        g_ypart + (((size_t)dq * B_DIM + b) * R_DIM + rh * R_HALF) * F_DIM) + f4;
    #pragma unroll
    for (int r = 0; r < R_HALF; r++) {
        ulonglong2 o; o.x = accXY[r]; o.y = accZW[r];
        yp[(size_t)r * (F_DIM / 4)] = o;
    }
}

// ---------------------------------------------------------------------------
// K5: y[b][r][f] = sum_dq y_part[dq][b][r][f]
// ---------------------------------------------------------------------------
__global__ void __launch_bounds__(128)
combine_kernel() {
    const int b = blockIdx.x, r = blockIdx.y;
    const int k = threadIdx.x;           // f4 index 0..127
    const size_t row = ((size_t)b * R_DIM + r) * F_DIM;
    ulonglong2 a; a.x = 0ull; a.y = 0ull;
    #pragma unroll
    for (int dq = 0; dq < NDQ; dq++) {
        const ulonglong2* yp = reinterpret_cast<const ulonglong2*>(
            g_ypart + ((size_t)dq * B_DIM * R_DIM) * F_DIM + row);
        ulonglong2 p = yp[k];
        a.x = add2(a.x, p.x);
        a.y = add2(a.y, p.y);
    }
    reinterpret_cast<ulonglong2*>(g_y + row)[k] = a;
}

// ---------------------------------------------------------------------------
// K6 stage B: out[b][j][f] = sum_r cb[j][r] * y[b][r][f]
// grid (16 j-tiles, B, 4 f-quarters) = 2048 CTAs. 8 warps; warp w owns
// j in [w*16, w*16+16); lane covers one f4-col of this quarter (32 f4).
// ---------------------------------------------------------------------------
__global__ void __launch_bounds__(256)
stageB_kernel(float* __restrict__ out) {
    __shared__ __align__(16) float sy[R_DIM * (F_DIM / 4)];   // 5 KB
    __shared__ __align__(16) float2 scb2[128 * R_DIM];        // 10 KB, {c,c}
    const int jt = blockIdx.x, b = blockIdx.y, fh = blockIdx.z;
    const int tid = threadIdx.x;
    const int wid = tid >> 5, lane = tid & 31;
    const int FQ = F_DIM / 4;     // 128 floats per quarter

    for (int k = tid; k < R_DIM * FQ; k += 256) {
        int r = k / FQ, f = k - r * FQ;
        sy[k] = g_y[(size_t)b * R_DIM * F_DIM + (size_t)r * F_DIM + fh * FQ + f];
    }
    for (int k = tid; k < 128 * R_DIM; k += 256) {
        int j = k / R_DIM, r = k - j * R_DIM;
        float c = g_cb[(size_t)(jt * 128 + j) * R_PAD + r];
        scb2[k] = make_float2(c, c);
    }
    __syncthreads();

    float* ob = out + ((size_t)b * D_DIM + jt * 128) * F_DIM + fh * FQ;

    const int f4 = lane;              // 0..31 within this quarter
    ull yXY[R_DIM], yZW[R_DIM];
    #pragma unroll
    for (int r = 0; r < R_DIM; r++) {
        ulonglong2 v = reinterpret_cast<const ulonglong2*>(&sy[r * FQ])[f4];
        yXY[r] = v.x; yZW[r] = v.y;
    }
    #pragma unroll 2
    for (int ji = 0; ji < 16; ji++) {
        const int jl = wid * 16 + ji;
        const ulonglong2* cp = reinterpret_cast<const ulonglong2*>(
            scb2 + jl * R_DIM);
        ulonglong2 u0 = cp[0], u1 = cp[1], u2 = cp[2], u3 = cp[3], u4 = cp[4];
        const ull c[R_DIM] = {u0.x, u0.y, u1.x, u1.y, u2.x,
                              u2.y, u3.x, u3.y, u4.x, u4.y};
        ull oXY = 0ull, oZW = 0ull;
        #pragma unroll
        for (int r = 0; r < R_DIM; r++) {
            oXY = fma2(yXY[r], c[r], oXY);
            oZW = fma2(yZW[r], c[r], oZW);
        }
        ulonglong2 o; o.x = oXY; o.y = oZW;
        reinterpret_cast<ulonglong2*>(ob + (size_t)jl * F_DIM)[f4] = o;
    }
}

// ---------------------------------------------------------------------------
// launch
// ---------------------------------------------------------------------------
extern "C" void kernel_launch(void* const* d_in, const int* in_sizes, int n_in,
                              void* d_out, int out_size) {
    const float* x;
    const float* s;
    if (in_sizes[0] == D_DIM) {
        s = (const float*)d_in[0];
        x = (const float*)d_in[1];
    } else {
        x = (const float*)d_in[0];
        s = (const float*)d_in[1];
    }
    float* out = (float*)d_out;

    abssum_kernel<<<D_DIM / 256, 256>>>(s);
    moments_kernel<<<1, 1024>>>(s);
    coeff_kernel<<<D_DIM / 256, 256>>>(s);
    stageA_kernel<<<dim3(NDQ, B_DIM), 256>>>(x);
    combine_kernel<<<dim3(B_DIM, R_DIM), 128>>>();
    stageB_kernel<<<dim3(D_DIM / 128, B_DIM, 4), 256>>>(out);
}

// round 17
// speedup vs baseline: 1.2913x; 1.1118x over previous
#include <cuda_runtime.h>
#include <cstdint>
#include <cstddef>

// Problem dims
#define D_DIM 2048
#define F_DIM 512
#define B_DIM 32
#define R_DIM 10          // Taylor terms r = 0..9 (|z| <= ~2.05)
#define R_HALF 5          // r-split: 5 terms per thread-half
#define R_PAD 12          // storage stride for coeff arrays
#define NDQ 16            // d-slices for stage A partials (128 d per slice)
#define TD 8              // d-rows per cp.async tile
#define NT (128 / TD)     // 16 tiles per slice

typedef unsigned long long ull;

// Scratch
__device__ float g_abssum[D_DIM];
__device__ float g_gj[D_DIM];                          // exp(-abs_sum_j)
__device__ float g_m[R_DIM];                           // moments sum_j g_j v_j^r
__device__ __align__(16) float g_ca[D_DIM * R_PAD];    // u_d^r / Z_d
__device__ __align__(16) float g_cb[D_DIM * R_PAD];    // g_j * v_j^r / r!
__device__ __align__(16) float g_ypart[(size_t)NDQ * B_DIM * R_DIM * F_DIM];
__device__ __align__(16) float g_y[(size_t)B_DIM * R_DIM * F_DIM];

__constant__ float c_invfact[R_DIM] = {
    1.0f, 1.0f, 0.5f, 1.0f/6.0f, 1.0f/24.0f, 1.0f/120.0f,
    1.0f/720.0f, 1.0f/5040.0f, 1.0f/40320.0f, 1.0f/362880.0f};

// ---------------------------------------------------------------------------
// packed f32x2 + cp.async helpers
// ---------------------------------------------------------------------------
__device__ __forceinline__ ull fma2(ull a, ull b, ull c) {
    ull d;
    asm("fma.rn.f32x2 %0, %1, %2, %3;" : "=l"(d) : "l"(a), "l"(b), "l"(c));
    return d;
}
__device__ __forceinline__ ull add2(ull a, ull b) {
    ull d;
    asm("add.rn.f32x2 %0, %1, %2;" : "=l"(d) : "l"(a), "l"(b));
    return d;
}
__device__ __forceinline__ uint32_t smem_u32(const void* p) {
    uint32_t a;
    asm("{ .reg .u64 t; cvta.to.shared.u64 t, %1; cvt.u32.u64 %0, t; }" : "=r"(a) : "l"(p));
    return a;
}
__device__ __forceinline__ void cp_async16(uint32_t dst, const void* src) {
    asm volatile("cp.async.cg.shared.global [%0], [%1], 16;\n" ::"r"(dst), "l"(src));
}
__device__ __forceinline__ void cp_commit() { asm volatile("cp.async.commit_group;\n"); }
template <int N>
__device__ __forceinline__ void cp_wait() {
    asm volatile("cp.async.wait_group %0;\n" ::"n"(N));
}

__device__ __forceinline__ float warpSum(float v) {
    #pragma unroll
    for (int o = 16; o; o >>= 1) v += __shfl_xor_sync(0xffffffffu, v, o);
    return v;
}

// ---------------------------------------------------------------------------
// K1: abs_sum[j] = sum_k |s[j] - s[k]|, and g_j = exp(-abs_sum[j])
// ---------------------------------------------------------------------------
__global__ void abssum_kernel(const float* __restrict__ s) {
    __shared__ float ss[D_DIM];
    int tid = threadIdx.x;
    for (int k = tid; k < D_DIM; k += 256) ss[k] = s[k];
    __syncthreads();
    int j = blockIdx.x * 256 + tid;
    float sj = ss[j];
    float a0 = 0.f, a1 = 0.f, a2 = 0.f, a3 = 0.f;
    #pragma unroll 4
    for (int k = 0; k < D_DIM; k += 4) {
        a0 += fabsf(sj - ss[k + 0]);
        a1 += fabsf(sj - ss[k + 1]);
        a2 += fabsf(sj - ss[k + 2]);
        a3 += fabsf(sj - ss[k + 3]);
    }
    float a = (a0 + a1) + (a2 + a3);
    g_abssum[j] = a;
    g_gj[j] = expf(-a);
}

// ---------------------------------------------------------------------------
// K2: single CTA. moments m[r] = sum_j g_j * v_j^r  (v_j = 1024*s_j)
// ---------------------------------------------------------------------------
__global__ void __launch_bounds__(1024)
moments_kernel(const float* __restrict__ s) {
    __shared__ float red[32][R_DIM];
    int tid = threadIdx.x, warp = tid >> 5, lane = tid & 31;

    float m[R_DIM];
    #pragma unroll
    for (int r = 0; r < R_DIM; r++) m[r] = 0.f;

    #pragma unroll
    for (int h = 0; h < 2; h++) {
        int j = tid + h * 1024;
        float g = g_gj[j];
        float v = 1024.0f * s[j];
        float p = g;
        #pragma unroll
        for (int r = 0; r < R_DIM; r++) { m[r] += p; p *= v; }
    }
    #pragma unroll
    for (int r = 0; r < R_DIM; r++) {
        float v = warpSum(m[r]);
        if (lane == 0) red[warp][r] = v;
    }
    __syncthreads();
    if (tid < R_DIM) {
        float a = 0.f;
        #pragma unroll
        for (int w = 0; w < 32; w++) a += red[w][tid];
        g_m[tid] = a;
    }
}

// ---------------------------------------------------------------------------
// K3: per-index coefficients (one thread per i)
// ---------------------------------------------------------------------------
__global__ void coeff_kernel(const float* __restrict__ s) {
    int i = blockIdx.x * 256 + threadIdx.x;
    float u = (2047.0f - 2.0f * (float)i) * (1.0f / 1024.0f);
    float up[R_DIM];
    up[0] = 1.0f;
    #pragma unroll
    for (int r = 1; r < R_DIM; r++) up[r] = up[r - 1] * u;
    float Z = 0.f;
    #pragma unroll
    for (int r = 0; r < R_DIM; r++) Z = fmaf(up[r] * c_invfact[r], g_m[r], Z);
    float winv = 1.0f / Z;

    float v = 1024.0f * s[i];
    float pv = g_gj[i];
    #pragma unroll
    for (int r = 0; r < R_DIM; r++) {
        g_ca[i * R_PAD + r] = winv * up[r];
        g_cb[i * R_PAD + r] = pv * c_invfact[r];
        pv *= v;
    }
}

// ---------------------------------------------------------------------------
// K4 stage A: y_part[dq][b][r][f] = sum_{d in slice of 128} ca[d][r]*x[b][d][f]
// grid (NDQ, B) = (16, 32), 256 thr = 128 f4-cols x 2 r-halves (r=0..4 / 5..9).
// x staged through smem via cp.async double buffer (tile = 8 d-rows x 512 f);
// gmem reads each line ONCE, both halves consume from smem. f32x2 FMA.
// ---------------------------------------------------------------------------
__global__ void __launch_bounds__(256)
stageA_kernel(const float* __restrict__ x) {
    __shared__ __align__(16) float2 sca2[2 * 128 * 6];        // 12 KB, {c,c}
    __shared__ __align__(16) float xs[2][TD * F_DIM];         // 32 KB
    const int dq = blockIdx.x, b = blockIdx.y;
    const int tid = threadIdx.x;
    const int d0 = dq * 128;

    // per-thread cp.async granule assignment (16B granules; 1024 per tile)
    uint32_t sdst[4];
    const float* gsrc[4];
    {
        const float* xb = x + ((size_t)b * D_DIM + d0) * F_DIM;
        #pragma unroll
        for (int i = 0; i < 4; i++) {
            int g = tid + i * 256;
            int row = g >> 7, col4 = (g & 127) * 4;   // 128 granules per row
            sdst[i] = smem_u32(&xs[0][row * F_DIM + col4]);
            gsrc[i] = xb + (size_t)row * F_DIM + col4;
        }
    }
    const uint32_t stage_step = (uint32_t)(TD * F_DIM * sizeof(float));

    auto load_tile = [&](int t, int st) {
        const size_t goff = (size_t)t * TD * F_DIM;
        const uint32_t soff = (uint32_t)st * stage_step;
        #pragma unroll
        for (int i = 0; i < 4; i++)
            cp_async16(sdst[i] + soff, gsrc[i] + goff);
        cp_commit();
    };

    load_tile(0, 0);   // overlap first tile load with coeff staging

    for (int k = tid; k < 128 * R_DIM; k += 256) {
        int d = k / R_DIM, r = k - d * R_DIM;
        float c = g_ca[(size_t)(d0 + d) * R_PAD + r];
        int rh = r / R_HALF, rr = r - rh * R_HALF;
        sca2[(rh * 128 + d) * 6 + rr] = make_float2(c, c);
    }

    const int f4 = tid & 127;
    const int rh = tid >> 7;          // 0: r=0..4, 1: r=5..9
    const ull* cbase = reinterpret_cast<const ull*>(sca2 + rh * 128 * 6);

    ull accXY[R_HALF], accZW[R_HALF];
    #pragma unroll
    for (int r = 0; r < R_HALF; r++) { accXY[r] = 0ull; accZW[r] = 0ull; }

    #pragma unroll 1
    for (int t = 0; t < NT; t++) {
        const int st = t & 1;
        if (t + 1 < NT) {
            load_tile(t + 1, st ^ 1);
            cp_wait<1>();
        } else {
            cp_wait<0>();
        }
        __syncthreads();

        const ulonglong2* xrow = reinterpret_cast<const ulonglong2*>(xs[st]) + f4;
        const ull* cp = cbase + (t * TD) * 6;
        #pragma unroll
        for (int dd = 0; dd < TD; dd++) {
            ulonglong2 xv = xrow[dd * (F_DIM / 4)];
            ulonglong2 p01 = *reinterpret_cast<const ulonglong2*>(cp + dd * 6);
            ulonglong2 p23 = *reinterpret_cast<const ulonglong2*>(cp + dd * 6 + 2);
            ull p4 = cp[dd * 6 + 4];
            const ull c[R_HALF] = {p01.x, p01.y, p23.x, p23.y, p4};
            #pragma unroll
            for (int r = 0; r < R_HALF; r++) {
                accXY[r] = fma2(xv.x, c[r], accXY[r]);
                accZW[r] = fma2(xv.y, c[r], accZW[r]);
            }
        }
        __syncthreads();   // protect buffer st before iteration t+1 reloads it
    }

    ulonglong2* yp = reinterpret_cast<ulonglong2*>(
        g_ypart + (((size_t)dq * B_DIM + b) * R_DIM + rh * R_HALF) * F_DIM) + f4;
    #pragma unroll
    for (int r = 0; r < R_HALF; r++) {
        ulonglong2 o; o.x = accXY[r]; o.y = accZW[r];
        yp[(size_t)r * (F_DIM / 4)] = o;
    }
}

// ---------------------------------------------------------------------------
// K5: y[b][r][f] = sum_dq y_part[dq][b][r][f]
// ---------------------------------------------------------------------------
__global__ void __launch_bounds__(128)
combine_kernel() {
    const int b = blockIdx.x, r = blockIdx.y;
    const int k = threadIdx.x;           // f4 index 0..127
    const size_t row = ((size_t)b * R_DIM + r) * F_DIM;
    ulonglong2 a; a.x = 0ull; a.y = 0ull;
    #pragma unroll
    for (int dq = 0; dq < NDQ; dq++) {
        const ulonglong2* yp = reinterpret_cast<const ulonglong2*>(
            g_ypart + ((size_t)dq * B_DIM * R_DIM) * F_DIM + row);
        ulonglong2 p = yp[k];
        a.x = add2(a.x, p.x);
        a.y = add2(a.y, p.y);
    }
    reinterpret_cast<ulonglong2*>(g_y + row)[k] = a;
}

// ---------------------------------------------------------------------------
// K6 stage B: out[b][j][f] = sum_r cb[j][r] * y[b][r][f]
// grid (16 j-tiles, B, 4 f-quarters) = 2048 CTAs.
// ---------------------------------------------------------------------------
__global__ void __launch_bounds__(256)
stageB_kernel(float* __restrict__ out) {
    __shared__ __align__(16) float sy[R_DIM * (F_DIM / 4)];   // 5 KB
    __shared__ __align__(16) float2 scb2[128 * R_DIM];        // 10 KB, {c,c}
    const int jt = blockIdx.x, b = blockIdx.y, fh = blockIdx.z;
    const int tid = threadIdx.x;
    const int wid = tid >> 5, lane = tid & 31;
    const int FQ = F_DIM / 4;     // 128 floats per quarter

    for (int k = tid; k < R_DIM * FQ; k += 256) {
        int r = k / FQ, f = k - r * FQ;
        sy[k] = g_y[(size_t)b * R_DIM * F_DIM + (size_t)r * F_DIM + fh * FQ + f];
    }
    for (int k = tid; k < 128 * R_DIM; k += 256) {
        int j = k / R_DIM, r = k - j * R_DIM;
        float c = g_cb[(size_t)(jt * 128 + j) * R_PAD + r];
        scb2[k] = make_float2(c, c);
    }
    __syncthreads();

    float* ob = out + ((size_t)b * D_DIM + jt * 128) * F_DIM + fh * FQ;

    const int f4 = lane;              // 0..31 within this quarter
    ull yXY[R_DIM], yZW[R_DIM];
    #pragma unroll
    for (int r = 0; r < R_DIM; r++) {
        ulonglong2 v = reinterpret_cast<const ulonglong2*>(&sy[r * FQ])[f4];
        yXY[r] = v.x; yZW[r] = v.y;
    }
    #pragma unroll 2
    for (int ji = 0; ji < 16; ji++) {
        const int jl = wid * 16 + ji;
        const ulonglong2* cp = reinterpret_cast<const ulonglong2*>(
            scb2 + jl * R_DIM);
        ulonglong2 u0 = cp[0], u1 = cp[1], u2 = cp[2], u3 = cp[3], u4 = cp[4];
        const ull c[R_DIM] = {u0.x, u0.y, u1.x, u1.y, u2.x,
                              u2.y, u3.x, u3.y, u4.x, u4.y};
        ull oXY = 0ull, oZW = 0ull;
        #pragma unroll
        for (int r = 0; r < R_DIM; r++) {
            oXY = fma2(yXY[r], c[r], oXY);
            oZW = fma2(yZW[r], c[r], oZW);
        }
        ulonglong2 o; o.x = oXY; o.y = oZW;
        reinterpret_cast<ulonglong2*>(ob + (size_t)jl * F_DIM)[f4] = o;
    }
}

// ---------------------------------------------------------------------------
// launch
// ---------------------------------------------------------------------------
extern "C" void kernel_launch(void* const* d_in, const int* in_sizes, int n_in,
                              void* d_out, int out_size) {
    const float* x;
    const float* s;
    if (in_sizes[0] == D_DIM) {
        s = (const float*)d_in[0];
        x = (const float*)d_in[1];
    } else {
        x = (const float*)d_in[0];
        s = (const float*)d_in[1];
    }
    float* out = (float*)d_out;

    abssum_kernel<<<D_DIM / 256, 256>>>(s);
    moments_kernel<<<1, 1024>>>(s);
    coeff_kernel<<<D_DIM / 256, 256>>>(s);
    stageA_kernel<<<dim3(NDQ, B_DIM), 256>>>(x);
    combine_kernel<<<dim3(B_DIM, R_DIM), 128>>>();
    stageB_kernel<<<dim3(D_DIM / 128, B_DIM, 4), 256>>>(out);
}